// round 5
// baseline (speedup 1.0000x reference)
#include <cuda_runtime.h>
#include <math.h>

#define NLAYER 5
#define HID    128
#define BAT    32
#define TIN    512
#define TTOT   514      // 512 given + 2 autoregressive continuation steps
#define NB0    8        // blocks for layer 0 (16 units each)
#define NBL    16       // blocks for layers 1..4 (8 units each)
#define HEAD_BID 72
#define GRID_N 73
#define NTHR   512
#define SMEM_BYTES 74240

// persistent device state (allocation-free scratch)
__device__ float g_h[NLAYER][TTOT][HID][BAT];   // hidden states, [unit][batch]
__device__ float g_xpred[2][BAT];               // predicted inputs for t=512,513
__device__ int   g_cnt[NLAYER][TTOT];           // per (layer,t) completion counters
__device__ int   g_xdone[2];

__global__ void zero_flags_kernel() {
    int i = blockIdx.x * blockDim.x + threadIdx.x;
    if (i < NLAYER * TTOT) ((int*)g_cnt)[i] = 0;
    if (i < 2) g_xdone[i] = 0;
}

__device__ __forceinline__ int ld_acq(const int* p) {
    int v;
    asm volatile("ld.acquire.gpu.global.b32 %0, [%1];" : "=r"(v) : "l"(p));
    return v;
}
__device__ __forceinline__ void red_rel(int* p) {
    asm volatile("red.release.gpu.global.add.s32 [%0], 1;" :: "l"(p));
}

__device__ __forceinline__ float2 ffma2(float w, float2 h, float2 acc) {
    union { float2 f; unsigned long long u; } A, B, C, D;
    A.f = make_float2(w, w); B.f = h; C.f = acc;
    asm("fma.rn.f32x2 %0, %1, %2, %3;" : "=l"(D.u) : "l"(A.u), "l"(B.u), "l"(C.u));
    return D.f;
}

__device__ __forceinline__ float sigm(float v) { return 1.0f / (1.0f + expf(-v)); }

__global__ void __launch_bounds__(NTHR, 1) lstm_main(
    const float* __restrict__ x,    const float* __restrict__ Wih0,
    const float* __restrict__ Wihr, const float* __restrict__ Whh,
    const float* __restrict__ bih,  const float* __restrict__ bhh,
    const float* __restrict__ W1,   const float* __restrict__ b1,
    const float* __restrict__ W2,   const float* __restrict__ b2,
    float* __restrict__ out)
{
    extern __shared__ float smem[];
    float*  sW = smem;                       // 8192 floats (32 KB)
    float2* sH = (float2*)(smem + 8192);     // 4096 float2 (32 KB)
    float2* sG = (float2*)(smem + 16384);    // up to 1024 float2 (8 KB)
    float*  sB = smem + 18432;               // 64
    float*  sWx = sB + 64;                   // 64

    const int tid = threadIdx.x;
    const int bid = blockIdx.x;

    // ================= HEAD BLOCK =================
    if (bid == HEAD_BID) {
        float* zsm  = smem;          // 32 x 129
        float* z2sm = smem + 4224;   // 32 x 129
        for (int m = 0; m < 3; m++) {
            int t = 511 + m;
            if (tid == 0) {
                while (ld_acq(&g_cnt[4][t]) < NBL) __nanosleep(64);
            }
            __syncthreads();
            // z = relu(h4[t]), transpose [k][b] -> zsm[b][k]
            for (int i = tid; i < HID * BAT; i += NTHR) {
                int k = i >> 5, b = i & 31;
                zsm[b * 129 + k] = fmaxf(g_h[4][t][k][b], 0.0f);
            }
            __syncthreads();
            // z2 = relu(z @ W1 + b1): thread (jg 0..15, b 0..31), 8 outputs each
            {
                int jg = tid >> 5, b = tid & 31;
                float acc[8];
                #pragma unroll
                for (int jj = 0; jj < 8; jj++) acc[jj] = b1[jg * 8 + jj];
                for (int k = 0; k < HID; k++) {
                    float zv = zsm[b * 129 + k];
                    const float4* wr = (const float4*)(W1 + k * HID + jg * 8);
                    #pragma unroll
                    for (int q = 0; q < 2; q++) {
                        float4 w = wr[q];
                        acc[q*4+0] += w.x * zv; acc[q*4+1] += w.y * zv;
                        acc[q*4+2] += w.z * zv; acc[q*4+3] += w.w * zv;
                    }
                }
                #pragma unroll
                for (int jj = 0; jj < 8; jj++)
                    z2sm[b * 129 + jg * 8 + jj] = fmaxf(acc[jj], 0.0f);
            }
            __syncthreads();
            // out = z2 @ W2 + b2 : 512 items (ob, oo)
            {
                int ob = tid >> 4, oo = tid & 15;
                float s = b2[oo];
                for (int j = 0; j < HID; j++)
                    s += z2sm[ob * 129 + j] * W2[j * 16 + oo];
                if (m == 2) {
                    out[ob * 18 + 2 + oo] = s;
                } else if (oo == 15) {
                    out[ob * 18 + m] = s;
                    g_xpred[m][ob] = s;
                }
            }
            __syncthreads();
            if (m < 2 && tid == 0) red_rel(&g_xdone[m]);
        }
        return;
    }

    // ================= LSTM LAYER BLOCKS =================
    int layer, u0, NB;
    if (bid < NB0) { layer = 0; NB = NB0; u0 = bid * 16; }
    else {
        layer = 1 + (bid - NB0) / NBL;
        NB = NBL; u0 = ((bid - NB0) % NBL) * 8;
    }
    const int NBbelow = (layer == 1) ? NB0 : NBL;

    // ---- stage weights into SMEM (once) ----
    if (layer == 0) {
        // 64 rows (16 units x 4 gates) x 128 K
        for (int i = tid; i < 64 * 128; i += NTHR) {
            int r = i >> 7, k = i & 127;
            int R = (r >> 4) * HID + u0 + (r & 15);
            sW[r * 128 + k] = Whh[R * HID + k];
        }
        if (tid < 64) {
            int R = (tid >> 4) * HID + u0 + (tid & 15);
            sWx[tid] = Wih0[R];
            sB[tid]  = bih[R] + bhh[R];
        }
    } else {
        // 32 rows (8 units x 4 gates) x 256 K (128 ih | 128 hh)
        const float* wih = Wihr + (size_t)(layer - 1) * 512 * HID;
        const float* whh = Whh  + (size_t)layer * 512 * HID;
        for (int i = tid; i < 32 * 256; i += NTHR) {
            int r = i >> 8, k = i & 255;
            int R = (r >> 3) * HID + u0 + (r & 7);
            sW[r * 256 + k] = (k < 128) ? wih[R * HID + k] : whh[R * HID + (k - 128)];
        }
        if (tid < 32) {
            int R = (tid >> 3) * HID + u0 + (tid & 7);
            sB[tid] = bih[layer * 512 + R] + bhh[layer * 512 + R];
        }
    }
    __syncthreads();

    const int bp = tid & 15;          // batch-pair index
    const int rr = tid >> 4;          // row (layers>=1: 0..31) / row-base (layer0)
    const bool isact = (layer == 0) ? (tid < 256) : (tid < 128);
    const int  au    = (layer == 0) ? (tid >> 4) : (tid >> 4); // unit idx for act
    float2 cst = make_float2(0.0f, 0.0f);

    for (int t = 0; t < TTOT; t++) {
        // ---- wait (tid0 only, acquire + backoff) ----
        if (tid == 0) {
            for (;;) {
                bool ok = true;
                if (t > 0 && ld_acq(&g_cnt[layer][t - 1]) < NB) ok = false;
                if (ok) {
                    if (layer > 0) {
                        if (ld_acq(&g_cnt[layer - 1][t]) < NBbelow) ok = false;
                    } else if (t >= TIN) {
                        if (ld_acq(&g_xdone[t - TIN]) < 1) ok = false;
                    }
                }
                if (ok) break;
                __nanosleep(64);
            }
        }
        __syncthreads();

        // ---- staging: below h(t) [k4 0..31] then prev h(t-1) [k4 32..63] ----
        {
            float4* dst = (float4*)sH;
            if (layer > 0) {
                const float4* srcB = (const float4*)&g_h[layer - 1][t][0][0];
                dst[tid] = srcB[tid];
                dst[tid + 512] = srcB[tid + 512];
                if (t > 0) {
                    const float4* srcP = (const float4*)&g_h[layer][t - 1][0][0];
                    dst[tid + 1024] = srcP[tid];
                    dst[tid + 1536] = srcP[tid + 512];
                }
            } else if (t > 0) {
                const float4* srcP = (const float4*)&g_h[layer][t - 1][0][0];
                dst[tid] = srcP[tid];
                dst[tid + 512] = srcP[tid + 512];
            }
        }
        __syncthreads();

        if (layer > 0) {
            float2 a0 = make_float2(sB[rr], sB[rr]);
            const float4* w4 = (const float4*)(sW + rr * 256);
            int n4 = (t > 0) ? 64 : 32;
            #pragma unroll 8
            for (int k4 = 0; k4 < n4; k4++) {
                float4 wv = w4[k4];
                const float2* hp = sH + k4 * 64 + bp;
                a0 = ffma2(wv.x, hp[0],  a0);
                a0 = ffma2(wv.y, hp[16], a0);
                a0 = ffma2(wv.z, hp[32], a0);
                a0 = ffma2(wv.w, hp[48], a0);
            }
            sG[rr * 16 + bp] = a0;
        } else {
            // rows rr and rr+32
            float2 a0 = make_float2(sB[rr], sB[rr]);
            float2 a1 = make_float2(sB[rr + 32], sB[rr + 32]);
            if (t > 0) {
                const float4* w40 = (const float4*)(sW + rr * 128);
                const float4* w41 = (const float4*)(sW + (rr + 32) * 128);
                #pragma unroll 8
                for (int k4 = 0; k4 < 32; k4++) {
                    float4 wa = w40[k4], wb = w41[k4];
                    const float2* hp = sH + k4 * 64 + bp;
                    float2 h0 = hp[0], h1 = hp[16], h2 = hp[32], h3 = hp[48];
                    a0 = ffma2(wa.x, h0, a0); a1 = ffma2(wb.x, h0, a1);
                    a0 = ffma2(wa.y, h1, a0); a1 = ffma2(wb.y, h1, a1);
                    a0 = ffma2(wa.z, h2, a0); a1 = ffma2(wb.z, h2, a1);
                    a0 = ffma2(wa.w, h3, a0); a1 = ffma2(wb.w, h3, a1);
                }
            }
            float2 xv;
            if (t < TIN)
                xv = make_float2(x[(2 * bp) * TIN + t], x[(2 * bp + 1) * TIN + t]);
            else
                xv = make_float2(g_xpred[t - TIN][2 * bp], g_xpred[t - TIN][2 * bp + 1]);
            a0 = ffma2(sWx[rr], xv, a0);
            a1 = ffma2(sWx[rr + 32], xv, a1);
            sG[rr * 16 + bp] = a0;
            sG[(rr + 32) * 16 + bp] = a1;
        }
        __syncthreads();

        // ---- activation + publish h ----
        if (isact) {
            int U = (layer == 0) ? 16 : 8;
            float2 gi = sG[(0 * U + au) * 16 + bp];
            float2 gf = sG[(1 * U + au) * 16 + bp];
            float2 gg = sG[(2 * U + au) * 16 + bp];
            float2 go = sG[(3 * U + au) * 16 + bp];
            float2 hout;
            {
                float iv = sigm(gi.x), fv = sigm(gf.x);
                float gv = tanhf(gg.x), ov = sigm(go.x);
                cst.x = fv * cst.x + iv * gv;
                hout.x = ov * tanhf(cst.x);
            }
            {
                float iv = sigm(gi.y), fv = sigm(gf.y);
                float gv = tanhf(gg.y), ov = sigm(go.y);
                cst.y = fv * cst.y + iv * gv;
                hout.y = ov * tanhf(cst.y);
            }
            *(float2*)&g_h[layer][t][u0 + au][2 * bp] = hout;
        }
        __syncthreads();
        if (tid == 0) red_rel(&g_cnt[layer][t]);   // release: orders prior h stores
    }
}

extern "C" void kernel_launch(void* const* d_in, const int* in_sizes, int n_in,
                              void* d_out, int out_size) {
    const float* x    = (const float*)d_in[0];
    // d_in[1] = future (fixed 18)
    const float* Wih0 = (const float*)d_in[2];
    const float* Wihr = (const float*)d_in[3];
    const float* Whh  = (const float*)d_in[4];
    const float* bih  = (const float*)d_in[5];
    const float* bhh  = (const float*)d_in[6];
    const float* W1   = (const float*)d_in[7];
    const float* b1   = (const float*)d_in[8];
    const float* W2   = (const float*)d_in[9];
    const float* b2   = (const float*)d_in[10];
    float* out = (float*)d_out;

    static bool attr_set = false;
    if (!attr_set) {
        cudaFuncSetAttribute(lstm_main, cudaFuncAttributeMaxDynamicSharedMemorySize,
                             SMEM_BYTES);
        attr_set = true;
    }

    zero_flags_kernel<<<6, 512>>>();
    lstm_main<<<GRID_N, NTHR, SMEM_BYTES>>>(x, Wih0, Wihr, Whh, bih, bhh,
                                            W1, b1, W2, b2, out);
}

// round 6
// speedup vs baseline: 1.5339x; 1.5339x over previous
#include <cuda_runtime.h>
#include <math.h>

#define NLAYER 5
#define HID    128
#define BAT    32
#define TIN    512
#define TTOT   514      // 512 given + 2 autoregressive continuation steps
#define NB0    16       // blocks for layer 0 (8 units each)
#define NBL    32       // blocks for layers 1..4 (4 units each)
#define HEAD_BID 144
#define GRID_N 145
#define NTHR   256
#define SMEM_BYTES 53760

// persistent device state (allocation-free scratch)
__device__ float g_h[NLAYER][TTOT][HID][BAT];   // hidden states, [unit][batch]
__device__ float g_xpred[2][BAT];               // predicted inputs for t=512,513
__device__ int   g_cnt[NLAYER][TTOT];           // per (layer,t) completion counters
__device__ int   g_xdone[2];

__global__ void zero_flags_kernel() {
    int i = blockIdx.x * blockDim.x + threadIdx.x;
    if (i < NLAYER * TTOT) ((int*)g_cnt)[i] = 0;
    if (i < 2) g_xdone[i] = 0;
}

// hard busy-wait: acquire load, no sleep (all threads of the block call this)
__device__ __forceinline__ void wait_ge(const int* p, int tgt) {
    int v;
    do {
        asm volatile("ld.acquire.gpu.global.b32 %0, [%1];" : "=r"(v) : "l"(p));
    } while (v < tgt);
}
__device__ __forceinline__ void red_rel(int* p) {
    asm volatile("red.release.gpu.global.add.s32 [%0], 1;" :: "l"(p));
}

__device__ __forceinline__ float2 ffma2(float w, float2 h, float2 acc) {
    union { float2 f; unsigned long long u; } A, B, C, D;
    A.f = make_float2(w, w); B.f = h; C.f = acc;
    asm("fma.rn.f32x2 %0, %1, %2, %3;" : "=l"(D.u) : "l"(A.u), "l"(B.u), "l"(C.u));
    return D.f;
}

__device__ __forceinline__ float sigm(float v) { return 1.0f / (1.0f + expf(-v)); }

__global__ void __launch_bounds__(NTHR, 1) lstm_main(
    const float* __restrict__ x,    const float* __restrict__ Wih0,
    const float* __restrict__ Wihr, const float* __restrict__ Whh,
    const float* __restrict__ bih,  const float* __restrict__ bhh,
    const float* __restrict__ W1,   const float* __restrict__ b1,
    const float* __restrict__ W2,   const float* __restrict__ b2,
    float* __restrict__ out)
{
    extern __shared__ float smem[];
    float*  sW  = smem;                        // up to 4096 floats (16 KB)
    float2* sH  = (float2*)(smem + 4096);      // up to 4096 float2 (32 KB)
    float2* sG  = (float2*)(smem + 12288);     // up to 512 float2 (4 KB)
    float*  sB  = smem + 13312;                // 32
    float*  sWx = sB + 32;                     // 32

    const int tid = threadIdx.x;
    const int bid = blockIdx.x;

    // ================= HEAD BLOCK =================
    if (bid == HEAD_BID) {
        float* zsm  = smem;          // 32 x 129
        float* z2sm = smem + 4224;   // 32 x 129
        for (int m = 0; m < 3; m++) {
            int t = 511 + m;
            wait_ge(&g_cnt[4][t], NBL);
            // z = relu(h4[t]), transpose [k][b] -> zsm[b][k]
            for (int i = tid; i < HID * BAT; i += NTHR) {
                int k = i >> 5, b = i & 31;
                zsm[b * 129 + k] = fmaxf(g_h[4][t][k][b], 0.0f);
            }
            __syncthreads();
            // z2 = relu(z @ W1 + b1): thread (jg 0..7, b 0..31), 16 outputs each
            {
                int jg = tid >> 5, b = tid & 31;
                float acc[16];
                #pragma unroll
                for (int jj = 0; jj < 16; jj++) acc[jj] = b1[jg * 16 + jj];
                for (int k = 0; k < HID; k++) {
                    float zv = zsm[b * 129 + k];
                    const float4* wr = (const float4*)(W1 + k * HID + jg * 16);
                    #pragma unroll
                    for (int q = 0; q < 4; q++) {
                        float4 w = wr[q];
                        acc[q*4+0] += w.x * zv; acc[q*4+1] += w.y * zv;
                        acc[q*4+2] += w.z * zv; acc[q*4+3] += w.w * zv;
                    }
                }
                #pragma unroll
                for (int jj = 0; jj < 16; jj++)
                    z2sm[b * 129 + jg * 16 + jj] = fmaxf(acc[jj], 0.0f);
            }
            __syncthreads();
            // out = z2 @ W2 + b2 : 512 items (ob, oo)
            for (int cc = tid; cc < BAT * 16; cc += NTHR) {
                int ob = cc >> 4, oo = cc & 15;
                float s = b2[oo];
                for (int j = 0; j < HID; j++)
                    s += z2sm[ob * 129 + j] * W2[j * 16 + oo];
                if (m == 2) {
                    out[ob * 18 + 2 + oo] = s;
                } else if (oo == 15) {
                    out[ob * 18 + m] = s;
                    g_xpred[m][ob] = s;
                }
            }
            __syncthreads();
            if (m < 2 && tid == 0) red_rel(&g_xdone[m]);
        }
        return;
    }

    // ================= LSTM LAYER BLOCKS =================
    int layer, u0, NB;
    if (bid < NB0) { layer = 0; NB = NB0; u0 = bid * 8; }
    else {
        layer = 1 + (bid - NB0) / NBL;
        NB = NBL; u0 = ((bid - NB0) % NBL) * 4;
    }
    const int NBbelow = (layer == 1) ? NB0 : NBL;

    // ---- stage weights (once) ----
    if (layer == 0) {
        // 32 rows (gate*8+unit) x 128 K (hh only)
        for (int i = tid; i < 32 * 128; i += NTHR) {
            int r = i >> 7, k = i & 127;
            int R = (r >> 3) * HID + u0 + (r & 7);
            sW[r * 128 + k] = Whh[R * HID + k];
        }
        if (tid < 32) {
            int R = (tid >> 3) * HID + u0 + (tid & 7);
            sWx[tid] = Wih0[R];
            sB[tid]  = bih[R] + bhh[R];
        }
    } else {
        // 16 rows (gate*4+unit) x 256 K (128 ih | 128 hh)
        const float* wih = Wihr + (size_t)(layer - 1) * 512 * HID;
        const float* whh = Whh  + (size_t)layer * 512 * HID;
        for (int i = tid; i < 16 * 256; i += NTHR) {
            int r = i >> 8, k = i & 255;
            int R = (r >> 2) * HID + u0 + (r & 3);
            sW[r * 256 + k] = (k < 128) ? wih[R * HID + k] : whh[R * HID + (k - 128)];
        }
        if (tid < 16) {
            int R = (tid >> 2) * HID + u0 + (tid & 3);
            sB[tid] = bih[layer * 512 + R] + bhh[layer * 512 + R];
        }
    }
    __syncthreads();

    const int bp = tid & 15;          // batch-pair index
    const int rr = tid >> 4;          // 0..15
    const bool isact = (layer == 0) ? (tid < 128) : (tid < 64);
    const int  au    = (layer == 0) ? ((tid >> 4) & 7) : ((tid >> 4) & 3);
    float2 cst = make_float2(0.0f, 0.0f);

    for (int t = 0; t < TTOT; t++) {
        // ---- dependency wait: ALL threads busy-poll (no barrier needed after) ----
        if (layer > 0) {
            wait_ge(&g_cnt[layer - 1][t], NBbelow);
            if (t > 0) wait_ge(&g_cnt[layer][t - 1], NB);
        } else {
            if (t > 0)    wait_ge(&g_cnt[0][t - 1], NB0);
            if (t >= TIN) wait_ge(&g_xdone[t - TIN], 1);
        }

        // layer0: issue x load early to hide latency under staging+compute
        float2 xv = make_float2(0.f, 0.f);
        if (layer == 0) {
            if (t < TIN)
                xv = make_float2(x[(2 * bp) * TIN + t], x[(2 * bp + 1) * TIN + t]);
            else
                xv = make_float2(g_xpred[t - TIN][2 * bp], g_xpred[t - TIN][2 * bp + 1]);
        }

        // ---- staging into sH (k-major [k][bp] float2) ----
        {
            float4* dst = (float4*)sH;
            if (layer > 0) {
                const float4* srcB = (const float4*)&g_h[layer - 1][t][0][0];
                dst[tid] = srcB[tid];
                dst[tid + 256] = srcB[tid + 256];
                dst[tid + 512] = srcB[tid + 512];
                dst[tid + 768] = srcB[tid + 768];
                if (t > 0) {
                    const float4* srcP = (const float4*)&g_h[layer][t - 1][0][0];
                    dst[tid + 1024] = srcP[tid];
                    dst[tid + 1280] = srcP[tid + 256];
                    dst[tid + 1536] = srcP[tid + 512];
                    dst[tid + 1792] = srcP[tid + 768];
                }
            } else if (t > 0) {
                const float4* srcP = (const float4*)&g_h[0][t - 1][0][0];
                dst[tid] = srcP[tid];
                dst[tid + 256] = srcP[tid + 256];
                dst[tid + 512] = srcP[tid + 512];
                dst[tid + 768] = srcP[tid + 768];
            }
        }
        __syncthreads();   // barrier 1: staging visible

        if (layer > 0) {
            float2 a0 = make_float2(sB[rr], sB[rr]);
            float2 a1 = make_float2(0.f, 0.f);
            const float4* w4 = (const float4*)(sW + rr * 256);
            int n4 = (t > 0) ? 64 : 32;
            #pragma unroll 8
            for (int k4 = 0; k4 < n4; k4 += 2) {
                float4 wa = w4[k4], wb = w4[k4 + 1];
                const float2* hp = sH + k4 * 64 + bp;
                a0 = ffma2(wa.x, hp[0],   a0);
                a0 = ffma2(wa.y, hp[16],  a0);
                a0 = ffma2(wa.z, hp[32],  a0);
                a0 = ffma2(wa.w, hp[48],  a0);
                a1 = ffma2(wb.x, hp[64],  a1);
                a1 = ffma2(wb.y, hp[80],  a1);
                a1 = ffma2(wb.z, hp[96],  a1);
                a1 = ffma2(wb.w, hp[112], a1);
            }
            sG[rr * 16 + bp] = make_float2(a0.x + a1.x, a0.y + a1.y);
        } else {
            // rows rr (gates 0-1) and rr+16 (gates 2-3)
            float2 a0 = make_float2(sB[rr], sB[rr]);
            float2 a1 = make_float2(sB[rr + 16], sB[rr + 16]);
            if (t > 0) {
                const float4* w40 = (const float4*)(sW + rr * 128);
                const float4* w41 = (const float4*)(sW + (rr + 16) * 128);
                #pragma unroll 8
                for (int k4 = 0; k4 < 32; k4++) {
                    float4 wa = w40[k4], wb = w41[k4];
                    const float2* hp = sH + k4 * 64 + bp;
                    float2 h0 = hp[0], h1 = hp[16], h2 = hp[32], h3 = hp[48];
                    a0 = ffma2(wa.x, h0, a0); a1 = ffma2(wb.x, h0, a1);
                    a0 = ffma2(wa.y, h1, a0); a1 = ffma2(wb.y, h1, a1);
                    a0 = ffma2(wa.z, h2, a0); a1 = ffma2(wb.z, h2, a1);
                    a0 = ffma2(wa.w, h3, a0); a1 = ffma2(wb.w, h3, a1);
                }
            }
            a0 = ffma2(sWx[rr], xv, a0);
            a1 = ffma2(sWx[rr + 16], xv, a1);
            sG[rr * 16 + bp] = a0;
            sG[(rr + 16) * 16 + bp] = a1;
        }
        __syncthreads();   // barrier 2: gates ready, sH free

        // ---- activation + publish h ----
        if (isact) {
            int U = (layer == 0) ? 8 : 4;
            float2 gi = sG[(0 * U + au) * 16 + bp];
            float2 gf = sG[(1 * U + au) * 16 + bp];
            float2 gg = sG[(2 * U + au) * 16 + bp];
            float2 go = sG[(3 * U + au) * 16 + bp];
            float2 hout;
            {
                float iv = sigm(gi.x), fv = sigm(gf.x);
                float gv = tanhf(gg.x), ov = sigm(go.x);
                cst.x = fv * cst.x + iv * gv;
                hout.x = ov * tanhf(cst.x);
            }
            {
                float iv = sigm(gi.y), fv = sigm(gf.y);
                float gv = tanhf(gg.y), ov = sigm(go.y);
                cst.y = fv * cst.y + iv * gv;
                hout.y = ov * tanhf(cst.y);
            }
            *(float2*)&g_h[layer][t][u0 + au][2 * bp] = hout;
        }
        __syncthreads();   // barrier 3: h stores done block-wide
        if (tid == 0) red_rel(&g_cnt[layer][t]);   // release publish
    }
}

extern "C" void kernel_launch(void* const* d_in, const int* in_sizes, int n_in,
                              void* d_out, int out_size) {
    const float* x    = (const float*)d_in[0];
    // d_in[1] = future (fixed 18)
    const float* Wih0 = (const float*)d_in[2];
    const float* Wihr = (const float*)d_in[3];
    const float* Whh  = (const float*)d_in[4];
    const float* bih  = (const float*)d_in[5];
    const float* bhh  = (const float*)d_in[6];
    const float* W1   = (const float*)d_in[7];
    const float* b1   = (const float*)d_in[8];
    const float* W2   = (const float*)d_in[9];
    const float* b2   = (const float*)d_in[10];
    float* out = (float*)d_out;

    static bool attr_set = false;
    if (!attr_set) {
        cudaFuncSetAttribute(lstm_main, cudaFuncAttributeMaxDynamicSharedMemorySize,
                             SMEM_BYTES);
        attr_set = true;
    }

    zero_flags_kernel<<<11, 256>>>();
    lstm_main<<<GRID_N, NTHR, SMEM_BYTES>>>(x, Wih0, Wihr, Whh, bih, bhh,
                                            W1, b1, W2, b2, out);
}

// round 7
// speedup vs baseline: 1.6223x; 1.0576x over previous
#include <cuda_runtime.h>
#include <math.h>

#define NLAYER 5
#define HID    128
#define BAT    32
#define TIN    512
#define TTOT   514      // 512 given + 2 autoregressive continuation steps
#define NB0    16       // blocks for layer 0 (8 units each)
#define NBL    32       // blocks for layers 1..4 (4 units each)
#define HEAD_BID 144
#define GRID_N 145
#define NTHR   256
#define SMEM_BYTES 54016

// smem float offsets
#define OFF_W   0        // 4224 floats (layer0: 32 rows x stride132; l>=1: 16 x stride264)
#define OFF_H   4224     // 8192 floats (4096 float2, [k][bp])
#define OFF_G   12416    // 1024 floats (gate partials)
#define OFF_B   13440    // 32
#define OFF_WX  13472    // 32

// persistent device state
__device__ float g_h[NLAYER][TTOT][HID][BAT];   // hidden states [unit][batch]
__device__ float g_xpred[2][BAT];
__device__ int   g_cnt[NLAYER][TTOT];
__device__ int   g_xdone[2];

__global__ void zero_flags_kernel() {
    int i = blockIdx.x * blockDim.x + threadIdx.x;
    if (i < NLAYER * TTOT) ((int*)g_cnt)[i] = 0;
    if (i < 2) g_xdone[i] = 0;
}

__device__ __forceinline__ int ld_acq(const int* p) {
    int v;
    asm volatile("ld.acquire.gpu.global.b32 %0, [%1];" : "=r"(v) : "l"(p));
    return v;
}
__device__ __forceinline__ void red_rel(int* p) {
    asm volatile("red.release.gpu.global.add.s32 [%0], 1;" :: "l"(p));
}
__device__ __forceinline__ float2 ffma2(float w, float2 h, float2 acc) {
    union { float2 f; unsigned long long u; } A, B, C, D;
    A.f = make_float2(w, w); B.f = h; C.f = acc;
    asm("fma.rn.f32x2 %0, %1, %2, %3;" : "=l"(D.u) : "l"(A.u), "l"(B.u), "l"(C.u));
    return D.f;
}
__device__ __forceinline__ float sigm(float v) { return 1.0f / (1.0f + expf(-v)); }

__global__ void __launch_bounds__(NTHR, 1) lstm_main(
    const float* __restrict__ x,    const float* __restrict__ Wih0,
    const float* __restrict__ Wihr, const float* __restrict__ Whh,
    const float* __restrict__ bih,  const float* __restrict__ bhh,
    const float* __restrict__ W1,   const float* __restrict__ b1,
    const float* __restrict__ W2,   const float* __restrict__ b2,
    float* __restrict__ out)
{
    extern __shared__ float smem[];
    float*  sW  = smem + OFF_W;
    float2* sH  = (float2*)(smem + OFF_H);
    float*  sB  = smem + OFF_B;
    float*  sWx = smem + OFF_WX;

    const int tid = threadIdx.x;
    const int bid = blockIdx.x;

    // ================= HEAD BLOCK =================
    if (bid == HEAD_BID) {
        float* zsm  = smem;          // 32 x 129
        float* z2sm = smem + 4224;   // 32 x 129
        for (int m = 0; m < 3; m++) {
            int t = 511 + m;
            if (tid == 0) { while (ld_acq(&g_cnt[4][t]) < NBL) {} }
            __syncthreads();
            for (int i = tid; i < HID * BAT; i += NTHR) {
                int k = i >> 5, b = i & 31;
                zsm[b * 129 + k] = fmaxf(g_h[4][t][k][b], 0.0f);
            }
            __syncthreads();
            {
                int jg = tid >> 5, b = tid & 31;
                float acc[16];
                #pragma unroll
                for (int jj = 0; jj < 16; jj++) acc[jj] = b1[jg * 16 + jj];
                for (int k = 0; k < HID; k++) {
                    float zv = zsm[b * 129 + k];
                    const float4* wr = (const float4*)(W1 + k * HID + jg * 16);
                    #pragma unroll
                    for (int q = 0; q < 4; q++) {
                        float4 w = wr[q];
                        acc[q*4+0] += w.x * zv; acc[q*4+1] += w.y * zv;
                        acc[q*4+2] += w.z * zv; acc[q*4+3] += w.w * zv;
                    }
                }
                #pragma unroll
                for (int jj = 0; jj < 16; jj++)
                    z2sm[b * 129 + jg * 16 + jj] = fmaxf(acc[jj], 0.0f);
            }
            __syncthreads();
            for (int cc = tid; cc < BAT * 16; cc += NTHR) {
                int ob = cc >> 4, oo = cc & 15;
                float s = b2[oo];
                for (int j = 0; j < HID; j++)
                    s += z2sm[ob * 129 + j] * W2[j * 16 + oo];
                if (m == 2) {
                    out[ob * 18 + 2 + oo] = s;
                } else if (oo == 15) {
                    out[ob * 18 + m] = s;
                    g_xpred[m][ob] = s;
                }
            }
            __syncthreads();
            if (m < 2 && tid == 0) red_rel(&g_xdone[m]);
        }
        return;
    }

    // ================= LSTM LAYER BLOCKS =================
    int layer, u0, NB;
    if (bid < NB0) { layer = 0; NB = NB0; u0 = bid * 8; }
    else {
        layer = 1 + (bid - NB0) / NBL;
        NB = NBL; u0 = ((bid - NB0) % NBL) * 4;
    }
    const int NBbelow = (layer == 1) ? NB0 : NBL;

    // ---- stage weights (once); padded row strides to avoid LDS bank conflicts ----
    if (layer == 0) {
        // 32 rows (gate*8+unit) x 128 K (hh), row stride 132
        for (int i = tid; i < 32 * 128; i += NTHR) {
            int r = i >> 7, k = i & 127;
            int R = (r >> 3) * HID + u0 + (r & 7);
            sW[r * 132 + k] = Whh[R * HID + k];
        }
        if (tid < 32) {
            int R = (tid >> 3) * HID + u0 + (tid & 7);
            sWx[tid] = Wih0[R];
            sB[tid]  = bih[R] + bhh[R];
        }
    } else {
        // 16 rows (gate*4+unit) x 256 K (128 ih | 128 hh), row stride 264
        const float* wih = Wihr + (size_t)(layer - 1) * 512 * HID;
        const float* whh = Whh  + (size_t)layer * 512 * HID;
        for (int i = tid; i < 16 * 256; i += NTHR) {
            int r = i >> 8, k = i & 255;
            int R = (r >> 2) * HID + u0 + (r & 3);
            sW[r * 264 + k] = (k < 128) ? wih[R * HID + k] : whh[R * HID + (k - 128)];
        }
        if (tid < 16) {
            int R = (tid >> 2) * HID + u0 + (tid & 3);
            sB[tid] = bih[layer * 512 + R] + bhh[layer * 512 + R];
        }
    }
    __syncthreads();

    // thread roles
    const int bp = tid & 15;                 // layer0 compute / activation
    const int rr = tid >> 4;                 // layer0 row base
    // layers>=1 compute decomposition: (khalf, row, batch-quad)
    const int kh  = tid >> 7;                // 0..1
    const int rrq = (tid >> 3) & 15;         // 0..15
    const int bq  = tid & 7;                 // 0..7
    const bool isact = (layer == 0) ? (tid < 128) : (tid < 64);
    const int  au    = (layer == 0) ? ((tid >> 4) & 7) : ((tid >> 4) & 3);
    float2 cst = make_float2(0.0f, 0.0f);

    float2* sG2 = (float2*)(smem + OFF_G);
    float4* sG4 = (float4*)(smem + OFF_G);
    const float4* sH4 = (const float4*)(smem + OFF_H);

    for (int t = 0; t < TTOT; t++) {
        // ---- dependency wait: warp 0 only ----
        if (tid < 32) {
            const int* addr = &g_cnt[0][0]; int tgt = 0; bool need = false;
            if (layer > 0) {
                if (tid == 0) { addr = &g_cnt[layer - 1][t]; tgt = NBbelow; need = true; }
                if (tid == 1 && t > 0) { addr = &g_cnt[layer][t - 1]; tgt = NB; need = true; }
            } else {
                if (tid == 0 && t > 0) { addr = &g_cnt[0][t - 1]; tgt = NB0; need = true; }
                if (tid == 1 && t >= TIN) { addr = &g_xdone[t - TIN]; tgt = 1; need = true; }
            }
            bool done = !need;
            do {
                if (!done) done = (ld_acq(addr) >= tgt);
            } while (!__all_sync(0xffffffffu, done));
        }
        __syncthreads();

        float2 xv = make_float2(0.f, 0.f);
        if (layer == 0) {
            if (t < TIN)
                xv = make_float2(x[(2 * bp) * TIN + t], x[(2 * bp + 1) * TIN + t]);
            else
                xv = make_float2(g_xpred[t - TIN][2 * bp], g_xpred[t - TIN][2 * bp + 1]);
        }

        // ---- staging into sH ([k][b], b contiguous) ----
        {
            float4* dst = (float4*)sH;
            if (layer > 0) {
                const float4* srcB = (const float4*)&g_h[layer - 1][t][0][0];
                dst[tid]       = srcB[tid];
                dst[tid + 256] = srcB[tid + 256];
                dst[tid + 512] = srcB[tid + 512];
                dst[tid + 768] = srcB[tid + 768];
                if (t > 0) {
                    const float4* srcP = (const float4*)&g_h[layer][t - 1][0][0];
                    dst[tid + 1024] = srcP[tid];
                    dst[tid + 1280] = srcP[tid + 256];
                    dst[tid + 1536] = srcP[tid + 512];
                    dst[tid + 1792] = srcP[tid + 768];
                }
            } else if (t > 0) {
                const float4* srcP = (const float4*)&g_h[0][t - 1][0][0];
                dst[tid]       = srcP[tid];
                dst[tid + 256] = srcP[tid + 256];
                dst[tid + 512] = srcP[tid + 512];
                dst[tid + 768] = srcP[tid + 768];
            }
        }
        __syncthreads();   // staging visible

        if (layer > 0) {
            // partial gates: row rrq, batches [bq*4, bq*4+4), K half kh
            float2 a0, a1, b0, b1;
            if (kh == 0) { float bb = sB[rrq]; a0 = make_float2(bb, bb); a1 = a0; }
            else         { a0 = make_float2(0.f, 0.f); a1 = a0; }
            b0 = make_float2(0.f, 0.f); b1 = b0;
            if (kh == 0 || t > 0) {
                const float4* w4 = (const float4*)(sW + rrq * 264 + kh * 128);
                const float4* h4 = sH4 + kh * 1024 + bq;
                #pragma unroll 8
                for (int k4 = 0; k4 < 32; k4++) {
                    float4 wv = w4[k4];
                    float4 h0 = h4[(k4 * 4 + 0) * 8];
                    float4 h1 = h4[(k4 * 4 + 1) * 8];
                    float4 h2 = h4[(k4 * 4 + 2) * 8];
                    float4 h3 = h4[(k4 * 4 + 3) * 8];
                    a0 = ffma2(wv.x, make_float2(h0.x, h0.y), a0);
                    a1 = ffma2(wv.x, make_float2(h0.z, h0.w), a1);
                    b0 = ffma2(wv.y, make_float2(h1.x, h1.y), b0);
                    b1 = ffma2(wv.y, make_float2(h1.z, h1.w), b1);
                    a0 = ffma2(wv.z, make_float2(h2.x, h2.y), a0);
                    a1 = ffma2(wv.z, make_float2(h2.z, h2.w), a1);
                    b0 = ffma2(wv.w, make_float2(h3.x, h3.y), b0);
                    b1 = ffma2(wv.w, make_float2(h3.z, h3.w), b1);
                }
            }
            sG4[kh * 128 + rrq * 8 + bq] =
                make_float4(a0.x + b0.x, a0.y + b0.y, a1.x + b1.x, a1.y + b1.y);
        } else {
            // layer0: rows rr and rr+16, all 16 bp
            float2 a0 = make_float2(sB[rr], sB[rr]);
            float2 a1 = make_float2(sB[rr + 16], sB[rr + 16]);
            if (t > 0) {
                const float4* w40 = (const float4*)(sW + rr * 132);
                const float4* w41 = (const float4*)(sW + (rr + 16) * 132);
                #pragma unroll 8
                for (int k4 = 0; k4 < 32; k4++) {
                    float4 wa = w40[k4], wb = w41[k4];
                    const float2* hp = sH + k4 * 64 + bp;
                    float2 h0 = hp[0], h1 = hp[16], h2 = hp[32], h3 = hp[48];
                    a0 = ffma2(wa.x, h0, a0); a1 = ffma2(wb.x, h0, a1);
                    a0 = ffma2(wa.y, h1, a0); a1 = ffma2(wb.y, h1, a1);
                    a0 = ffma2(wa.z, h2, a0); a1 = ffma2(wb.z, h2, a1);
                    a0 = ffma2(wa.w, h3, a0); a1 = ffma2(wb.w, h3, a1);
                }
            }
            a0 = ffma2(sWx[rr], xv, a0);
            a1 = ffma2(sWx[rr + 16], xv, a1);
            sG2[rr * 16 + bp] = a0;
            sG2[(rr + 16) * 16 + bp] = a1;
        }
        __syncthreads();   // gates ready

        // ---- activation + publish h ----
        if (isact) {
            float2 gt[4];
            if (layer > 0) {
                #pragma unroll
                for (int g = 0; g < 4; g++) {
                    int row = g * 4 + au;
                    float4 p0 = sG4[row * 8 + (bp >> 1)];
                    float4 p1 = sG4[128 + row * 8 + (bp >> 1)];
                    if (bp & 1) gt[g] = make_float2(p0.z + p1.z, p0.w + p1.w);
                    else        gt[g] = make_float2(p0.x + p1.x, p0.y + p1.y);
                }
            } else {
                #pragma unroll
                for (int g = 0; g < 4; g++)
                    gt[g] = sG2[(g * 8 + au) * 16 + bp];
            }
            float2 hout;
            {
                float iv = sigm(gt[0].x), fv = sigm(gt[1].x);
                float gv = tanhf(gt[2].x), ov = sigm(gt[3].x);
                cst.x = fv * cst.x + iv * gv;
                hout.x = ov * tanhf(cst.x);
            }
            {
                float iv = sigm(gt[0].y), fv = sigm(gt[1].y);
                float gv = tanhf(gt[2].y), ov = sigm(gt[3].y);
                cst.y = fv * cst.y + iv * gv;
                hout.y = ov * tanhf(cst.y);
            }
            *(float2*)&g_h[layer][t][u0 + au][2 * bp] = hout;
        }
        __syncthreads();   // h stores done block-wide
        if (tid == 0) red_rel(&g_cnt[layer][t]);
    }
}

extern "C" void kernel_launch(void* const* d_in, const int* in_sizes, int n_in,
                              void* d_out, int out_size) {
    const float* x    = (const float*)d_in[0];
    const float* Wih0 = (const float*)d_in[2];
    const float* Wihr = (const float*)d_in[3];
    const float* Whh  = (const float*)d_in[4];
    const float* bih  = (const float*)d_in[5];
    const float* bhh  = (const float*)d_in[6];
    const float* W1   = (const float*)d_in[7];
    const float* b1   = (const float*)d_in[8];
    const float* W2   = (const float*)d_in[9];
    const float* b2   = (const float*)d_in[10];
    float* out = (float*)d_out;

    static bool attr_set = false;
    if (!attr_set) {
        cudaFuncSetAttribute(lstm_main, cudaFuncAttributeMaxDynamicSharedMemorySize,
                             SMEM_BYTES);
        attr_set = true;
    }

    zero_flags_kernel<<<11, 256>>>();
    lstm_main<<<GRID_N, NTHR, SMEM_BYTES>>>(x, Wih0, Wihr, Whh, bih, bhh,
                                            W1, b1, W2, b2, out);
}